// round 13
// baseline (speedup 1.0000x reference)
#include <cuda_runtime.h>
#include <cuda_fp16.h>
#include <cuda_bf16.h>
#include <cstdint>

#define NMAX 100000
#define EMAX 3400000
#define F 128
#define F4 32

// ---------------- scratch (module-load allocation, allowed) ----------------
__device__ int   g_outc[NMAX];
__device__ int   g_inc[NMAX];
__device__ int   g_fill[NMAX];
__device__ float g_outnorm[NMAX];
__device__ float g_innorm[NMAX];
__device__ int   g_rowptr[NMAX];
__device__ int   g_rowend[NMAX];
__device__ int   g_cursor;
__device__ int   g_colidx[EMAX];
__device__ __align__(16) __half g_yh[NMAX * F];    // fp16 features (gather source / gemm A)
__device__ __align__(16) __half g_aggh[NMAX * F];  // fp16 aggregated (gemm A)
__device__ __align__(16) __half g_w1h[F * F];
__device__ __align__(16) __half g_w2h[F * F];
__device__ __align__(16) __half g_wm1h[F * F];
__device__ __align__(16) __half g_wm2h[F * 64];

// ---------------- graph preprocessing ----------------
__global__ void k_zero(int n) {
    int i = blockIdx.x * blockDim.x + threadIdx.x;
    if (i < n) { g_outc[i] = 0; g_inc[i] = 0; }
    if (i == 0) g_cursor = 0;
}

// 4 edges per thread via int4
__global__ void k_count(const int* __restrict__ src, const int* __restrict__ dst, int e) {
    int i = blockIdx.x * blockDim.x + threadIdx.x;
    int e4 = e >> 2;
    if (i < e4) {
        int4 s = reinterpret_cast<const int4*>(src)[i];
        int4 d = reinterpret_cast<const int4*>(dst)[i];
        atomicAdd(&g_outc[s.x], 1); atomicAdd(&g_outc[s.y], 1);
        atomicAdd(&g_outc[s.z], 1); atomicAdd(&g_outc[s.w], 1);
        atomicAdd(&g_inc[d.x], 1);  atomicAdd(&g_inc[d.y], 1);
        atomicAdd(&g_inc[d.z], 1);  atomicAdd(&g_inc[d.w], 1);
    }
    int rem = e - (e4 << 2);
    if (i < rem) {
        atomicAdd(&g_outc[src[(e4 << 2) + i]], 1);
        atomicAdd(&g_inc[dst[(e4 << 2) + i]], 1);
    }
}

// fused: block scan of in-degrees + atomic base alloc + norms.
__global__ void k_scan_norm(int n) {
    __shared__ int s[256];
    __shared__ int base;
    int tid = threadIdx.x;
    int i = blockIdx.x * 256 + tid;
    int deg = (i < n) ? g_inc[i] : 0;
    s[tid] = deg;
    __syncthreads();
    #pragma unroll
    for (int off = 1; off < 256; off <<= 1) {
        int t = (tid >= off) ? s[tid - off] : 0;
        __syncthreads();
        s[tid] += t;
        __syncthreads();
    }
    if (tid == 255) base = atomicAdd(&g_cursor, s[255]);
    __syncthreads();
    if (i < n) {
        int p = base + s[tid] - deg;
        g_rowptr[i] = p;
        g_rowend[i] = p + deg;
        g_fill[i]   = p;
        float od = (float)max(g_outc[i], 1);
        float id = (float)max(deg, 1);
        g_outnorm[i] = 1.0f / sqrtf(od);
        g_innorm[i]  = 1.0f / sqrtf(id);
    }
}

__global__ void k_fill(const int* __restrict__ src, const int* __restrict__ dst, int e) {
    int i = blockIdx.x * blockDim.x + threadIdx.x;
    int e4 = e >> 2;
    if (i < e4) {
        int4 s = reinterpret_cast<const int4*>(src)[i];
        int4 d = reinterpret_cast<const int4*>(dst)[i];
        g_colidx[atomicAdd(&g_fill[d.x], 1)] = s.x;
        g_colidx[atomicAdd(&g_fill[d.y], 1)] = s.y;
        g_colidx[atomicAdd(&g_fill[d.z], 1)] = s.z;
        g_colidx[atomicAdd(&g_fill[d.w], 1)] = s.w;
    }
    int rem = e - (e4 << 2);
    if (i < rem) {
        int t = (e4 << 2) + i;
        g_colidx[atomicAdd(&g_fill[dst[t]], 1)] = src[t];
    }
}

// ---------------- all weights fp32 -> fp16 in one launch ----------------
__global__ void k_f2h_all(const float* __restrict__ a0, const float* __restrict__ a1,
                          const float* __restrict__ a2, const float* __restrict__ a3) {
    int i = blockIdx.x * blockDim.x + threadIdx.x;   // 0 .. 57343
    if (i < 16384)           g_w1h[i]          = __float2half(a0[i]);
    else if (i < 32768)      g_w2h[i - 16384]  = __float2half(a1[i - 16384]);
    else if (i < 49152)      g_wm1h[i - 32768] = __float2half(a2[i - 32768]);
    else if (i < 57344)      g_wm2h[i - 49152] = __float2half(a3[i - 49152]);
}

// ---------------- x * out_norm -> fp16 y ----------------
__global__ void k_scale_h(const float* __restrict__ in, int n) {
    int i = blockIdx.x * blockDim.x + threadIdx.x;
    if (i < n * F4) {
        float4 v = reinterpret_cast<const float4*>(in)[i];
        float sc = g_outnorm[i >> 5];
        __half2 h0 = __floats2half2_rn(v.x * sc, v.y * sc);
        __half2 h1 = __floats2half2_rn(v.z * sc, v.w * sc);
        uint2 o;
        o.x = *reinterpret_cast<uint32_t*>(&h0);
        o.y = *reinterpret_cast<uint32_t*>(&h1);
        reinterpret_cast<uint2*>(g_yh)[i] = o;
    }
}

// ---------------- SpMM over row range [row0,row1): warp per dst row ----------------
__global__ __launch_bounds__(256) void k_spmm_h(int row0, int row1) {
    int w = row0 + ((blockIdx.x * blockDim.x + threadIdx.x) >> 5);
    int lane = threadIdx.x & 31;
    if (w >= row1) return;
    int s = g_rowptr[w];
    int e = g_rowend[w];
    const uint2* __restrict__ yv = reinterpret_cast<const uint2*>(g_yh);
    float s0 = 0.f, s1 = 0.f, s2 = 0.f, s3 = 0.f;
    int i = s;
    for (; i + 4 <= e; i += 4) {
        int c0 = g_colidx[i], c1 = g_colidx[i + 1], c2 = g_colidx[i + 2], c3 = g_colidx[i + 3];
        uint2 u0 = yv[c0 * 32 + lane];
        uint2 u1 = yv[c1 * 32 + lane];
        uint2 u2 = yv[c2 * 32 + lane];
        uint2 u3 = yv[c3 * 32 + lane];
        #define ACCU(u) { \
            float2 f0 = __half22float2(*reinterpret_cast<__half2*>(&(u).x)); \
            float2 f1 = __half22float2(*reinterpret_cast<__half2*>(&(u).y)); \
            s0 += f0.x; s1 += f0.y; s2 += f1.x; s3 += f1.y; }
        ACCU(u0) ACCU(u1) ACCU(u2) ACCU(u3)
    }
    for (; i < e; i++) {
        uint2 u = yv[g_colidx[i] * 32 + lane];
        ACCU(u)
        #undef ACCU
    }
    float sc = g_innorm[w];
    __half2 h0 = __floats2half2_rn(s0 * sc, s1 * sc);
    __half2 h1 = __floats2half2_rn(s2 * sc, s3 * sc);
    uint2 o;
    o.x = *reinterpret_cast<uint32_t*>(&h0);
    o.y = *reinterpret_cast<uint32_t*>(&h1);
    reinterpret_cast<uint2*>(g_aggh)[w * 32 + lane] = o;
}

// ---------------- shared mma building blocks (WM=2, WN=4, MT=4 fixed) --------------
#define LDA 136
#define LDB 136

template <int NT>
__device__ __forceinline__ void mma_pass(const __half* As, const __half* Bs,
                                         int warpM, int warpN, int lane,
                                         float acc[4][NT][4]) {
    #pragma unroll
    for (int i = 0; i < 4; i++)
        #pragma unroll
        for (int j = 0; j < NT; j++)
            #pragma unroll
            for (int q = 0; q < 4; q++) acc[i][j][q] = 0.f;

    #pragma unroll
    for (int ks = 0; ks < 8; ks++) {
        int k0 = ks * 16;
        uint32_t af[4][4], bf[NT][2];
        #pragma unroll
        for (int i = 0; i < 4; i++) {
            const __half* p = As + (warpM * 64 + i * 16 + (lane & 15)) * LDA
                                 + k0 + ((lane >> 4) << 3);
            uint32_t sa = (uint32_t)__cvta_generic_to_shared(p);
            asm volatile("ldmatrix.sync.aligned.m8n8.x4.shared.b16 {%0,%1,%2,%3}, [%4];"
                         : "=r"(af[i][0]), "=r"(af[i][1]), "=r"(af[i][2]), "=r"(af[i][3])
                         : "r"(sa));
        }
        #pragma unroll
        for (int j = 0; j < NT; j++) {
            const __half* p = Bs + (k0 + (lane & 15)) * LDB + warpN * NT * 8 + j * 8;
            uint32_t sb = (uint32_t)__cvta_generic_to_shared(p);
            asm volatile("ldmatrix.sync.aligned.m8n8.x2.trans.shared.b16 {%0,%1}, [%2];"
                         : "=r"(bf[j][0]), "=r"(bf[j][1]) : "r"(sb));
        }
        #pragma unroll
        for (int i = 0; i < 4; i++)
            #pragma unroll
            for (int j = 0; j < NT; j++) {
                asm volatile(
                    "mma.sync.aligned.m16n8k16.row.col.f32.f16.f16.f32 "
                    "{%0,%1,%2,%3}, {%4,%5,%6,%7}, {%8,%9}, {%0,%1,%2,%3};\n"
                    : "+f"(acc[i][j][0]), "+f"(acc[i][j][1]),
                      "+f"(acc[i][j][2]), "+f"(acc[i][j][3])
                    : "r"(af[i][0]), "r"(af[i][1]), "r"(af[i][2]), "r"(af[i][3]),
                      "r"(bf[j][0]), "r"(bf[j][1]));
            }
    }
}

template <int NT>
__device__ __forceinline__ void epi_relu_to_smem(float acc[4][NT][4], const float* bias,
                                                 __half* As, int warpM, int warpN, int lane) {
    int g = lane >> 2, t = lane & 3;
    #pragma unroll
    for (int i = 0; i < 4; i++) {
        int rbase = warpM * 64 + i * 16 + g;
        #pragma unroll
        for (int j = 0; j < NT; j++) {
            int col = warpN * NT * 8 + j * 8 + 2 * t;
            float bv0 = bias[col], bv1 = bias[col + 1];
            #pragma unroll
            for (int hm = 0; hm < 2; hm++) {
                float v0 = fmaxf(acc[i][j][hm * 2 + 0] + bv0, 0.f);
                float v1 = fmaxf(acc[i][j][hm * 2 + 1] + bv1, 0.f);
                __half2 h = __floats2half2_rn(v0, v1);
                *reinterpret_cast<__half2*>(As + (rbase + hm * 8) * LDA + col) = h;
            }
        }
    }
}

__device__ __forceinline__ void load_b_tile(const __half* __restrict__ W, __half* Bs,
                                            int tid, int ncols8) {
    int nv = 128 * ncols8;
    for (int idx = tid; idx < nv; idx += 256) {
        int r = idx / ncols8, c = idx % ncols8;
        uint4 v = *reinterpret_cast<const uint4*>(W + (size_t)r * (ncols8 * 8) + c * 8);
        *reinterpret_cast<uint4*>(Bs + r * LDB + c * 8) = v;
    }
}

// ---------------- GEMM1: yh = fp16( relu(aggh@W1 + b1) * out_norm ) ----------------
__global__ __launch_bounds__(256) void k_gemm1(const float* __restrict__ bias, int M, int blk0) {
    extern __shared__ __half sm[];
    __half* As = sm;
    __half* Bs = sm + 128 * LDA;
    int tid = threadIdx.x, lane = tid & 31, wid = tid >> 5;
    int warpM = wid & 1, warpN = wid >> 1;
    int rowBase = (blk0 + blockIdx.x) * 128;

    for (int idx = tid; idx < 2048; idx += 256) {
        int r = idx >> 4, c = idx & 15;
        uint4 v = make_uint4(0u, 0u, 0u, 0u);
        if (rowBase + r < M)
            v = *reinterpret_cast<const uint4*>(g_aggh + (size_t)(rowBase + r) * 128 + c * 8);
        *reinterpret_cast<uint4*>(As + r * LDA + c * 8) = v;
    }
    load_b_tile(g_w1h, Bs, tid, 16);
    __syncthreads();

    float acc[4][4][4];
    mma_pass<4>(As, Bs, warpM, warpN, lane, acc);

    int g = lane >> 2, t = lane & 3;
    #pragma unroll
    for (int i = 0; i < 4; i++) {
        int rr = rowBase + warpM * 64 + i * 16 + g;
        #pragma unroll
        for (int j = 0; j < 4; j++) {
            int col = warpN * 32 + j * 8 + 2 * t;
            float bv0 = bias[col], bv1 = bias[col + 1];
            #pragma unroll
            for (int hm = 0; hm < 2; hm++) {
                int r = rr + hm * 8;
                if (r >= M) continue;
                float s = g_outnorm[r];
                float v0 = fmaxf(acc[i][j][hm * 2 + 0] + bv0, 0.f) * s;
                float v1 = fmaxf(acc[i][j][hm * 2 + 1] + bv1, 0.f) * s;
                __half2 h = __floats2half2_rn(v0, v1);
                *reinterpret_cast<__half2*>(g_yh + (size_t)r * 128 + col) = h;
            }
        }
    }
}

// ---------------- fused head: out = sigmoid(relu(relu(aggh@W2+b2)@Wm1+bm1)@Wm2+bm2) ----
__global__ __launch_bounds__(256) void k_fused_head(const float* __restrict__ b2,
                                                    const float* __restrict__ bm1,
                                                    const float* __restrict__ bm2,
                                                    float* __restrict__ out, int M, int blk0) {
    extern __shared__ __half sm[];
    __half* As = sm;
    __half* Bs = sm + 128 * LDA;
    int tid = threadIdx.x, lane = tid & 31, wid = tid >> 5;
    int warpM = wid & 1, warpN = wid >> 1;
    int rowBase = (blk0 + blockIdx.x) * 128;

    for (int idx = tid; idx < 2048; idx += 256) {
        int r = idx >> 4, c = idx & 15;
        uint4 v = make_uint4(0u, 0u, 0u, 0u);
        if (rowBase + r < M)
            v = *reinterpret_cast<const uint4*>(g_aggh + (size_t)(rowBase + r) * 128 + c * 8);
        *reinterpret_cast<uint4*>(As + r * LDA + c * 8) = v;
    }
    load_b_tile(g_w2h, Bs, tid, 16);
    __syncthreads();

    float acc[4][4][4];

    // stage 1: h2 = relu(A@W2 + b2) -> As
    mma_pass<4>(As, Bs, warpM, warpN, lane, acc);
    __syncthreads();
    epi_relu_to_smem<4>(acc, b2, As, warpM, warpN, lane);
    load_b_tile(g_wm1h, Bs, tid, 16);
    __syncthreads();

    // stage 2: m1 = relu(h2@Wm1 + bm1) -> As
    mma_pass<4>(As, Bs, warpM, warpN, lane, acc);
    __syncthreads();
    epi_relu_to_smem<4>(acc, bm1, As, warpM, warpN, lane);
    load_b_tile(g_wm2h, Bs, tid, 8);
    __syncthreads();

    // stage 3: out = sigmoid(m1@Wm2 + bm2) -> global fp32 [M,64]
    float acc2[4][2][4];
    mma_pass<2>(As, Bs, warpM, warpN, lane, acc2);

    int g = lane >> 2, t = lane & 3;
    #pragma unroll
    for (int i = 0; i < 4; i++) {
        int rr = rowBase + warpM * 64 + i * 16 + g;
        #pragma unroll
        for (int j = 0; j < 2; j++) {
            int col = warpN * 16 + j * 8 + 2 * t;
            float bv0 = bm2[col], bv1 = bm2[col + 1];
            #pragma unroll
            for (int hm = 0; hm < 2; hm++) {
                int r = rr + hm * 8;
                if (r >= M) continue;
                float v0 = acc2[i][j][hm * 2 + 0] + bv0;
                float v1 = acc2[i][j][hm * 2 + 1] + bv1;
                float2 o;
                o.x = 1.f / (1.f + __expf(-v0));
                o.y = 1.f / (1.f + __expf(-v1));
                *reinterpret_cast<float2*>(out + (size_t)r * 64 + col) = o;
            }
        }
    }
}

// ---------------- launch ----------------
extern "C" void kernel_launch(void* const* d_in, const int* in_sizes, int n_in,
                              void* d_out, int out_size) {
    const float* x   = (const float*)d_in[0];
    const int*   src = (const int*)d_in[1];
    const int*   dst = (const int*)d_in[2];
    const float* W1  = (const float*)d_in[3];
    const float* b1  = (const float*)d_in[4];
    const float* W2  = (const float*)d_in[5];
    const float* b2  = (const float*)d_in[6];
    const float* Wm1 = (const float*)d_in[7];
    const float* bm1 = (const float*)d_in[8];
    const float* Wm2 = (const float*)d_in[9];
    const float* bm2 = (const float*)d_in[10];
    float* out = (float*)d_out;

    int n = in_sizes[0] / F;     // 100000
    int e = in_sizes[1];         // 3200000

    // host objects created once (first call = correctness run, outside capture);
    // no device memory is allocated here.
    static cudaStream_t s1 = [] {
        cudaStream_t s; cudaStreamCreateWithFlags(&s, cudaStreamNonBlocking); return s;
    }();
    static cudaEvent_t evA = [] { cudaEvent_t ev; cudaEventCreateWithFlags(&ev, cudaEventDisableTiming); return ev; }();
    static cudaEvent_t evB = [] { cudaEvent_t ev; cudaEventCreateWithFlags(&ev, cudaEventDisableTiming); return ev; }();
    static cudaEvent_t evC = [] { cudaEvent_t ev; cudaEventCreateWithFlags(&ev, cudaEventDisableTiming); return ev; }();
    static cudaEvent_t evD = [] { cudaEvent_t ev; cudaEventCreateWithFlags(&ev, cudaEventDisableTiming); return ev; }();
    static cudaEvent_t evE = [] { cudaEvent_t ev; cudaEventCreateWithFlags(&ev, cudaEventDisableTiming); return ev; }();
    static cudaEvent_t evF = [] { cudaEvent_t ev; cudaEventCreateWithFlags(&ev, cudaEventDisableTiming); return ev; }();
    cudaStream_t s0 = 0;   // legacy default stream = capture stream

    const int SMEM = 2 * 128 * LDA * 2;   // 69632 bytes
    cudaFuncSetAttribute(k_gemm1, cudaFuncAttributeMaxDynamicSharedMemorySize, SMEM);
    cudaFuncSetAttribute(k_fused_head, cudaFuncAttributeMaxDynamicSharedMemorySize, SMEM);

    int nbN  = (n + 255) / 256;
    int nbE4 = ((e >> 2) + 255) / 256;
    int nbV  = (n * F4 + 255) / 256;
    int nbG  = (n + 127) / 128;           // 782
    int halfB = nbG / 2;                  // 391
    int rowSplit = halfB * 128;           // 50048
    int nbW0 = (rowSplit * 32 + 255) / 256;
    int nbW1 = ((n - rowSplit) * 32 + 255) / 256;

    // ---- preprocessing (s0), with scale/f2h overlapped under k_fill on s1 ----
    k_zero<<<nbN, 256, 0, s0>>>(n);
    k_count<<<nbE4, 256, 0, s0>>>(src, dst, e);
    k_scan_norm<<<nbN, 256, 0, s0>>>(n);
    cudaEventRecord(evA, s0);
    k_fill<<<nbE4, 256, 0, s0>>>(src, dst, e);

    cudaStreamWaitEvent(s1, evA, 0);
    k_f2h_all<<<(57344 + 255) / 256, 256, 0, s1>>>(W1, W2, Wm1, Wm2);
    k_scale_h<<<nbV, 256, 0, s1>>>(x, n);          // yh = fp16(x * out_norm)
    cudaEventRecord(evB, s1);
    cudaStreamWaitEvent(s0, evB, 0);

    // ---- conv1, pipelined halves: gemm1(h0) on s1 overlaps spmm1(h1) on s0 ----
    k_spmm_h<<<nbW0, 256, 0, s0>>>(0, rowSplit);
    cudaEventRecord(evC, s0);
    k_spmm_h<<<nbW1, 256, 0, s0>>>(rowSplit, n);
    cudaStreamWaitEvent(s1, evC, 0);
    k_gemm1<<<halfB, 256, SMEM, s1>>>(b1, n, 0);
    cudaEventRecord(evD, s1);
    k_gemm1<<<nbG - halfB, 256, SMEM, s0>>>(b1, n, halfB);
    cudaStreamWaitEvent(s0, evD, 0);               // join: spmm2 gathers arbitrary yh rows

    // ---- conv2 + fused MLP head, pipelined halves ----
    k_spmm_h<<<nbW0, 256, 0, s0>>>(0, rowSplit);
    cudaEventRecord(evE, s0);
    k_spmm_h<<<nbW1, 256, 0, s0>>>(rowSplit, n);
    cudaStreamWaitEvent(s1, evE, 0);
    k_fused_head<<<halfB, 256, SMEM, s1>>>(b2, bm1, bm2, out, n, 0);
    cudaEventRecord(evF, s1);
    k_fused_head<<<nbG - halfB, 256, SMEM, s0>>>(b2, bm1, bm2, out, n, halfB);
    cudaStreamWaitEvent(s0, evF, 0);               // final join back into capture stream
}